// round 14
// baseline (speedup 1.0000x reference)
#include <cuda_runtime.h>
#include <cstdint>

#define NB 4
#define NS 2048
#define ND 1024
#define NH 16
#define NDK 64
#define NBH (NB*NH)   /* 64 */
#define NM (NB*NS)    /* 8192 */

#define PLB ((size_t)NBH*NS*128)   /* bytes per 16-bit plane of one [BH,S,64] tensor */
#define ACTPB ((size_t)NM*ND*2)    /* bytes per fp16 activation plane [M,1024] */
#define WPB ((size_t)ND*ND*2)      /* bytes per fp16 weight plane */

#define LOG2E 1.4426950408889634f

// Scratch (allocation-free: __device__ globals)
__device__ __align__(128) uint8_t g_Qp[(size_t)NBH*NS*128];     // Q (fp16, *0.125*log2e)
__device__ __align__(128) uint8_t g_KV[2*(size_t)NBH*NS*128];   // K | V (fp16)
__device__ __align__(128) uint8_t g_act[3*ACTPB];               // q|k|v fp16
__device__ __align__(128) uint8_t g_w16[4*WPB];                 // wq|wk|wv|wo fp16
__device__ __align__(128) uint8_t g_ctx[ACTPB];                 // ctx fp16
__device__ float g_out[(size_t)NM*ND];
__device__ float g_l[NBH*NS];

// ===========================================================================
// helpers
// ===========================================================================
__device__ __forceinline__ uint32_t smem_u32(const void* p) {
    uint32_t a;
    asm("{ .reg .u64 t; cvta.to.shared.u64 t, %1; cvt.u32.u64 %0, t; }"
        : "=r"(a) : "l"(p));
    return a;
}
__device__ __forceinline__ float ex2(float x) {
    float r;
    asm("ex2.approx.ftz.f32 %0, %1;" : "=f"(r) : "f"(x));
    return r;
}
#define LDSM_X4(r0, r1, r2, r3, addr) \
    asm volatile("ldmatrix.sync.aligned.m8n8.x4.shared.b16 {%0,%1,%2,%3}, [%4];" \
                 : "=r"(r0), "=r"(r1), "=r"(r2), "=r"(r3) : "r"(addr))
#define LDSM_X4T(r0, r1, r2, r3, addr) \
    asm volatile("ldmatrix.sync.aligned.m8n8.x4.trans.shared.b16 {%0,%1,%2,%3}, [%4];" \
                 : "=r"(r0), "=r"(r1), "=r"(r2), "=r"(r3) : "r"(addr))

__device__ __forceinline__ void mma_f16(float* d, const uint32_t* a, const uint32_t* b) {
    asm volatile("mma.sync.aligned.m16n8k16.row.col.f32.f16.f16.f32 "
                 "{%0,%1,%2,%3}, {%4,%5,%6,%7}, {%8,%9}, {%0,%1,%2,%3};"
                 : "+f"(d[0]), "+f"(d[1]), "+f"(d[2]), "+f"(d[3])
                 : "r"(a[0]), "r"(a[1]), "r"(a[2]), "r"(a[3]),
                   "r"(b[0]), "r"(b[1]));
}

__device__ __forceinline__ uint32_t f16x2_pack(float x0, float x1) {
    uint32_t r;
    asm("cvt.rn.f16x2.f32 %0, %1, %2;" : "=r"(r) : "f"(x1), "f"(x0));
    return r;
}
#define SW128(off) ((off) ^ (((off) >> 3) & 0x70))

__device__ __forceinline__ void cp16(uint32_t dst, const uint8_t* src) {
    asm volatile("{ .reg .u64 gp; cvta.to.global.u64 gp, %1; "
                 "cp.async.cg.shared.global [%0], [gp], 16; }"
                 :: "r"(dst), "l"(src));
}
#define CP_COMMIT() asm volatile("cp.async.commit_group;" ::: "memory")
#define CP_WAIT1()  asm volatile("cp.async.wait_group 1;" ::: "memory")

__device__ __forceinline__ void stg_cs_f2(float* p, float x, float y) {
    asm volatile("st.global.cs.v2.f32 [%0], {%1,%2};"
                 :: "l"(p), "f"(x), "f"(y) : "memory");
}
__device__ __forceinline__ void stg_cs_f4(float* p, float x, float y, float z, float w) {
    asm volatile("st.global.cs.v4.f32 [%0], {%1,%2,%3,%4};"
                 :: "l"(p), "f"(x), "f"(y), "f"(z), "f"(w) : "memory");
}

// ===========================================================================
// Conversion pre-passes (single fp16 plane each)
// ===========================================================================
__global__ __launch_bounds__(256)
void conv_acts(const float* __restrict__ q, const float* __restrict__ k,
               const float* __restrict__ v, uint8_t* __restrict__ act)
{
    const int z = blockIdx.z;
    const float* src = (z == 0) ? q : (z == 1) ? k : v;
    size_t idx = (size_t)blockIdx.x * 256 + threadIdx.x;
    float4 x = ((const float4*)src)[idx];
    uint32_t a = f16x2_pack(x.x, x.y);
    uint32_t b = f16x2_pack(x.z, x.w);
    ((uint2*)act)[(size_t)z * (ACTPB / 8) + idx] = make_uint2(a, b);
}

__global__ __launch_bounds__(256)
void conv_ws(const float* __restrict__ wq, const float* __restrict__ wk,
             const float* __restrict__ wv, const float* __restrict__ wo,
             uint8_t* __restrict__ w16)
{
    const int z = blockIdx.z;
    const float* src = (z == 0) ? wq : (z == 1) ? wk : (z == 2) ? wv : wo;
    size_t idx = (size_t)blockIdx.x * 256 + threadIdx.x;
    float4 x = ((const float4*)src)[idx];
    uint32_t a = f16x2_pack(x.x, x.y);
    uint32_t b = f16x2_pack(x.z, x.w);
    ((uint2*)w16)[(size_t)z * (WPB / 8) + idx] = make_uint2(a, b);
}

// ===========================================================================
// fp16 GEMM on preconverted planes: C[m,n] = sum_k A[m,k] * W[n,k]
// BM=128, BN=128, BK=64 (128B fp16), 16 chunks, 2-stage cp.async pipeline.
// 256 threads = 8 warps as 4m x 2n; warp tile 32x64.
// Stage: A(16K) B(16K) = 32KB; x2 = 64KB dynamic smem.
// MODE 0: fp32 flat (+bias)*scale. MODE 1: fp16 plane head-split, (+bias)*scale.
// ===========================================================================
#define G2_STG 32768u

template<int MODE>
__device__ __forceinline__
void gemm2_body(const uint8_t* __restrict__ Ah, const uint8_t* __restrict__ Wh,
                const float* __restrict__ bias, void* __restrict__ Cout,
                float scale, uint32_t sb)
{
    const int tid  = threadIdx.x;
    const int wid  = tid >> 5, lane = tid & 31;
    const int m0 = blockIdx.y << 7;
    const int n0 = blockIdx.x << 7;
    const int mwOff = (wid & 3) * 32;
    const int nwOff = (wid >> 2) * 64;

    const int lrow = tid >> 3;        // 0..31
    const int lchk = tid & 7;

    // prologue: chunk 0 -> stage 0
    {
        const uint32_t st = sb;
#pragma unroll
        for (int rr = 0; rr < 4; rr++) {
            int row = rr*32 + lrow;
            uint32_t off = (uint32_t)(row*128 + lchk*16);
            cp16(st + SW128(off), Ah + (size_t)(m0 + row)*2048 + lchk*16);
        }
#pragma unroll
        for (int rr = 0; rr < 4; rr++) {
            int row = rr*32 + lrow;
            uint32_t off = (uint32_t)(row*128 + lchk*16);
            cp16(st + 16384 + SW128(off), Wh + (size_t)(n0 + row)*2048 + lchk*16);
        }
    }
    CP_COMMIT();

    float d[2][8][4];
#pragma unroll
    for (int mt = 0; mt < 2; mt++)
#pragma unroll
        for (int nt = 0; nt < 8; nt++)
#pragma unroll
            for (int e = 0; e < 4; e++) d[mt][nt][e] = 0.f;

    for (int ch = 0; ch < 16; ch++) {
        if (ch + 1 < 16) {
            const uint32_t st = sb + (uint32_t)((ch+1) & 1) * G2_STG;
            const int k0b = (ch + 1) * 128;
#pragma unroll
            for (int rr = 0; rr < 4; rr++) {
                int row = rr*32 + lrow;
                uint32_t off = (uint32_t)(row*128 + lchk*16);
                cp16(st + SW128(off), Ah + (size_t)(m0 + row)*2048 + k0b + lchk*16);
            }
#pragma unroll
            for (int rr = 0; rr < 4; rr++) {
                int row = rr*32 + lrow;
                uint32_t off = (uint32_t)(row*128 + lchk*16);
                cp16(st + 16384 + SW128(off),
                     Wh + (size_t)(n0 + row)*2048 + k0b + lchk*16);
            }
        }
        CP_COMMIT();
        CP_WAIT1();
        __syncthreads();

        const uint32_t cur = sb + (uint32_t)(ch & 1) * G2_STG;
#pragma unroll
        for (int ks = 0; ks < 4; ks++) {
            uint32_t aHi[2][4], bHi[4][4];
#pragma unroll
            for (int mt = 0; mt < 2; mt++) {
                uint32_t off = (uint32_t)((mwOff + mt*16 + (lane & 15))*128
                                          + ks*32 + (lane >> 4)*16);
                LDSM_X4(aHi[mt][0], aHi[mt][1], aHi[mt][2], aHi[mt][3],
                        cur + SW128(off));
            }
#pragma unroll
            for (int nt2 = 0; nt2 < 4; nt2++) {
                uint32_t off = (uint32_t)((nwOff + nt2*16 + (lane>>4)*8 + (lane&7))*128
                                          + ks*32 + ((lane>>3)&1)*16);
                LDSM_X4(bHi[nt2][0], bHi[nt2][1], bHi[nt2][2], bHi[nt2][3],
                        cur + 16384 + SW128(off));
            }
#pragma unroll
            for (int mt = 0; mt < 2; mt++) {
#pragma unroll
                for (int nt = 0; nt < 8; nt++) {
                    mma_f16(d[mt][nt], aHi[mt], &bHi[nt >> 1][(nt & 1) * 2]);
                }
            }
        }
        __syncthreads();
    }

    const int g = lane >> 2, tig = lane & 3;
#pragma unroll
    for (int mt = 0; mt < 2; mt++) {
#pragma unroll
        for (int nt = 0; nt < 8; nt++) {
            int col = n0 + nwOff + nt*8 + 2*tig;
            float2 bb = *(const float2*)&bias[col];
#pragma unroll
            for (int half = 0; half < 2; half++) {
                int row = m0 + mwOff + mt*16 + g + half*8;
                float ox = (d[mt][nt][half*2+0] + bb.x) * scale;
                float oy = (d[mt][nt][half*2+1] + bb.y) * scale;
                if (MODE == 0) {
                    *(float2*)((float*)Cout + (size_t)row * ND + col) = make_float2(ox, oy);
                } else {
                    int bb2 = row >> 11;
                    int ss  = row & (NS - 1);
                    int hh  = col >> 6;
                    int dd  = col & (NDK - 1);
                    size_t boff = ((size_t)(bb2*NH + hh)*NS + ss)*128 + dd*2;
                    *(uint32_t*)((uint8_t*)Cout + boff) = f16x2_pack(ox, oy);
                }
            }
        }
    }
}

__global__ __launch_bounds__(256)
void gemm_qkv3(const uint8_t* __restrict__ act, const uint8_t* __restrict__ w16,
               const float* __restrict__ bq, const float* __restrict__ bk,
               const float* __restrict__ bv,
               uint8_t* __restrict__ Qp, uint8_t* __restrict__ KVp)
{
    extern __shared__ uint8_t smraw[];
    const uint32_t sb = smem_u32(smraw);
    const int z = blockIdx.z;
    const uint8_t* Ah = act + (size_t)z * ACTPB;
    const uint8_t* Wh = w16 + (size_t)z * WPB;
    const float* bias = (z == 0) ? bq : (z == 1) ? bk : bv;
    uint8_t* out = (z == 0) ? Qp : (z == 1) ? KVp : (KVp + PLB);
    float scale = (z == 0) ? (0.125f * LOG2E) : 1.0f;
    gemm2_body<1>(Ah, Wh, bias, out, scale, sb);
}

__global__ __launch_bounds__(256)
void gemm_out2(const uint8_t* __restrict__ ctx, const uint8_t* __restrict__ w16,
               const float* __restrict__ bias, float* __restrict__ C)
{
    extern __shared__ uint8_t smraw[];
    const uint32_t sb = smem_u32(smraw);
    gemm2_body<0>(ctx, w16 + 3*WPB, bias, C, 1.0f, sb);
}

// ===========================================================================
// Attention pass 1: l = sum 2^s (no max — scores bounded).
// 128-wide k-tiles (ntiles = qb+1), computed in two 64-col halves.
// dyn smem: Q(16K) | Kstage0(16K) | Kstage1(16K) = 48KB
// ===========================================================================
__global__ __launch_bounds__(256)
void attn_pass1(const uint8_t* __restrict__ Qp, const uint8_t* __restrict__ KV,
                float* __restrict__ gl)
{
    extern __shared__ uint8_t smraw[];
    const uint32_t sb = smem_u32(smraw);
    const uint32_t QH = sb;
    const uint32_t KST = sb + 16384;

    const int qb = gridDim.x - 1 - blockIdx.x;
    const int bh = blockIdx.y;
    const int tid = threadIdx.x, w = tid >> 5, lane = tid & 31;
    const int g = lane >> 2, tig = lane & 3;

    const uint8_t* Qg = Qp + (size_t)bh*NS*128 + (size_t)qb*128*128;
    const uint8_t* Kg = KV + (size_t)bh*NS*128;

#pragma unroll
    for (int rr = 0; rr < 4; rr++) {
        int idx = rr*256 + tid;
        int row = idx >> 3, chk = idx & 7;
        uint32_t off = (uint32_t)(row*128 + chk*16);
        cp16(QH + SW128(off), Qg + off);
    }
    CP_COMMIT();
#pragma unroll
    for (int rr = 0; rr < 4; rr++) {
        int idx = rr*256 + tid;
        int row = idx >> 3, chk = idx & 7;
        uint32_t off = (uint32_t)(row*128 + chk*16);
        cp16(KST + SW128(off), Kg + off);
    }
    CP_COMMIT();
    CP_WAIT1();
    __syncthreads();

    uint32_t aQh[4][4];
#pragma unroll
    for (int ks = 0; ks < 4; ks++) {
        uint32_t off = (uint32_t)((w*16 + (lane & 15))*128 + ks*32 + (lane>>4)*16);
        LDSM_X4(aQh[ks][0], aQh[ks][1], aQh[ks][2], aQh[ks][3], QH + SW128(off));
    }

    const int ntiles = qb + 1;
    const int r0 = qb*128 + w*16 + g, r1 = r0 + 8;
    float l0 = 0.f, l1 = 0.f;

    for (int kt = 0; kt < ntiles; kt++) {
        if (kt + 1 < ntiles) {
            uint32_t st = KST + ((kt+1)&1)*16384;
#pragma unroll
            for (int rr = 0; rr < 4; rr++) {
                int idx = rr*256 + tid;
                int row = idx >> 3, chk = idx & 7;
                uint32_t off = (uint32_t)(row*128 + chk*16);
                cp16(st + SW128(off), Kg + (size_t)((kt+1)*128+row)*128 + chk*16);
            }
        }
        CP_COMMIT();
        CP_WAIT1();
        __syncthreads();

        const uint32_t KHs = KST + (kt&1)*16384;
#pragma unroll
        for (int half = 0; half < 2; half++) {
            float c[8][4];
#pragma unroll
            for (int n8 = 0; n8 < 8; n8++)
#pragma unroll
                for (int e = 0; e < 4; e++) c[n8][e] = 0.f;

#pragma unroll
            for (int ks = 0; ks < 4; ks++) {
#pragma unroll
                for (int np = 0; np < 4; np++) {
                    uint32_t off = (uint32_t)((half*64 + np*16 + (lane>>4)*8 + (lane&7))*128
                                              + ks*32 + ((lane>>3)&1)*16);
                    uint32_t bh4[4];
                    LDSM_X4(bh4[0], bh4[1], bh4[2], bh4[3], KHs + SW128(off));
                    mma_f16(c[np*2],   aQh[ks], &bh4[0]);
                    mma_f16(c[np*2+1], aQh[ks], &bh4[2]);
                }
            }

            if (kt == ntiles - 1) {
#pragma unroll
                for (int n8 = 0; n8 < 8; n8++) {
                    int col = kt*128 + half*64 + n8*8 + 2*tig;
                    if (col   > r0) c[n8][0] = -1e30f;
                    if (col+1 > r0) c[n8][1] = -1e30f;
                    if (col   > r1) c[n8][2] = -1e30f;
                    if (col+1 > r1) c[n8][3] = -1e30f;
                }
            }

#pragma unroll
            for (int n8 = 0; n8 < 8; n8++) {
                l0 += ex2(c[n8][0]) + ex2(c[n8][1]);
                l1 += ex2(c[n8][2]) + ex2(c[n8][3]);
            }
        }
        __syncthreads();
    }

    l0 += __shfl_xor_sync(0xffffffffu, l0, 1);
    l0 += __shfl_xor_sync(0xffffffffu, l0, 2);
    l1 += __shfl_xor_sync(0xffffffffu, l1, 1);
    l1 += __shfl_xor_sync(0xffffffffu, l1, 2);

    if (tig == 0) {
        gl[(size_t)bh*NS + r0] = l0;
        gl[(size_t)bh*NS + r1] = l1;
    }
}

// ===========================================================================
// Attention pass 2: recompute S identically, p = 2^s / l, write attn
// (streaming), O += P@V. ctx emitted as single fp16 plane.
// Zero-fill of masked upper region in tail (overlaps with compute of other
// CTAs in the wave).
// dyn smem: Q(16K) + 2 stages x (K 8K | V 8K) = 48KB
// ===========================================================================
__global__ __launch_bounds__(256)
void attn_pass2(const uint8_t* __restrict__ Qp, const uint8_t* __restrict__ KV,
                const float* __restrict__ gl,
                float* __restrict__ attn, uint8_t* __restrict__ ctx,
                int write_attn)
{
    extern __shared__ uint8_t smraw[];
    const uint32_t sb = smem_u32(smraw);
    const uint32_t QH = sb;
    const uint32_t ST = sb + 16384;

    const int qb = gridDim.x - 1 - blockIdx.x;
    const int bh = blockIdx.y;
    const int tid = threadIdx.x, w = tid >> 5, lane = tid & 31;
    const int g = lane >> 2, tig = lane & 3;

    const uint8_t* Qg = Qp + (size_t)bh*NS*128 + (size_t)qb*128*128;
    const uint8_t* Kg = KV + (size_t)bh*NS*128;

#pragma unroll
    for (int rr = 0; rr < 4; rr++) {
        int idx = rr*256 + tid;
        int row = idx >> 3, chk = idx & 7;
        uint32_t off = (uint32_t)(row*128 + chk*16);
        cp16(QH + SW128(off), Qg + off);
    }
    CP_COMMIT();
#pragma unroll
    for (int rr = 0; rr < 4; rr++) {
        int idx = rr*256 + tid;
        int pl = idx >> 9, wi = idx & 511;
        int row = wi >> 3, chk = wi & 7;
        uint32_t off = (uint32_t)(row*128 + chk*16);
        cp16(ST + pl*8192 + SW128(off), Kg + (size_t)pl*PLB + off);
    }
    CP_COMMIT();
    CP_WAIT1();
    __syncthreads();

    uint32_t aQh[4][4];
#pragma unroll
    for (int ks = 0; ks < 4; ks++) {
        uint32_t off = (uint32_t)((w*16 + (lane & 15))*128 + ks*32 + (lane>>4)*16);
        LDSM_X4(aQh[ks][0], aQh[ks][1], aQh[ks][2], aQh[ks][3], QH + SW128(off));
    }

    const int ntiles = 2*qb + 2;
    const int r0 = qb*128 + w*16 + g, r1 = r0 + 8;
    const float il0 = 1.0f / gl[(size_t)bh*NS + r0];
    const float il1 = 1.0f / gl[(size_t)bh*NS + r1];

    float oc[8][4];
#pragma unroll
    for (int n8 = 0; n8 < 8; n8++)
#pragma unroll
        for (int e = 0; e < 4; e++) oc[n8][e] = 0.f;

    for (int kt = 0; kt < ntiles; kt++) {
        if (kt + 1 < ntiles) {
            uint32_t st = ST + ((kt+1)&1)*16384;
#pragma unroll
            for (int rr = 0; rr < 4; rr++) {
                int idx = rr*256 + tid;
                int pl = idx >> 9, wi = idx & 511;
                int row = wi >> 3, chk = wi & 7;
                uint32_t off = (uint32_t)(row*128 + chk*16);
                cp16(st + pl*8192 + SW128(off),
                     Kg + (size_t)pl*PLB + (size_t)((kt+1)*64+row)*128 + chk*16);
            }
        }
        CP_COMMIT();
        CP_WAIT1();
        __syncthreads();

        const uint32_t B0 = ST + (kt&1)*16384;
        const uint32_t KHs = B0, VHs = B0 + 8192;

        float c[8][4];
#pragma unroll
        for (int n8 = 0; n8 < 8; n8++)
#pragma unroll
            for (int e = 0; e < 4; e++) c[n8][e] = 0.f;

#pragma unroll
        for (int ks = 0; ks < 4; ks++) {
#pragma unroll
            for (int np = 0; np < 4; np++) {
                uint32_t off = (uint32_t)((np*16 + (lane>>4)*8 + (lane&7))*128
                                          + ks*32 + ((lane>>3)&1)*16);
                uint32_t bh4[4];
                LDSM_X4(bh4[0], bh4[1], bh4[2], bh4[3], KHs + SW128(off));
                mma_f16(c[np*2],   aQh[ks], &bh4[0]);
                mma_f16(c[np*2+1], aQh[ks], &bh4[2]);
            }
        }

        if (kt >= 2*qb) {
#pragma unroll
            for (int n8 = 0; n8 < 8; n8++) {
                int col = kt*64 + n8*8 + 2*tig;
                if (col   > r0) c[n8][0] = -1e30f;
                if (col+1 > r0) c[n8][1] = -1e30f;
                if (col   > r1) c[n8][2] = -1e30f;
                if (col+1 > r1) c[n8][3] = -1e30f;
            }
        }

#pragma unroll
        for (int n8 = 0; n8 < 8; n8++) {
            c[n8][0] = ex2(c[n8][0])*il0;
            c[n8][1] = ex2(c[n8][1])*il0;
            c[n8][2] = ex2(c[n8][2])*il1;
            c[n8][3] = ex2(c[n8][3])*il1;
        }

        if (write_attn) {
            size_t ro0 = ((size_t)bh*NS + r0)*NS + (size_t)kt*64;
            size_t ro1 = ((size_t)bh*NS + r1)*NS + (size_t)kt*64;
#pragma unroll
            for (int n8 = 0; n8 < 8; n8++) {
                int col = n8*8 + 2*tig;
                stg_cs_f2(attn + ro0 + col, c[n8][0], c[n8][1]);
                stg_cs_f2(attn + ro1 + col, c[n8][2], c[n8][3]);
            }
        }

        // P @ V
#pragma unroll
        for (int ks = 0; ks < 4; ks++) {
            uint32_t pH[4];
            pH[0] = f16x2_pack(c[2*ks][0],   c[2*ks][1]);
            pH[1] = f16x2_pack(c[2*ks][2],   c[2*ks][3]);
            pH[2] = f16x2_pack(c[2*ks+1][0], c[2*ks+1][1]);
            pH[3] = f16x2_pack(c[2*ks+1][2], c[2*ks+1][3]);
#pragma unroll
            for (int np = 0; np < 4; np++) {
                uint32_t off = (uint32_t)((ks*16 + ((lane>>3)&1)*8 + (lane&7))*128
                                          + np*32 + (lane>>4)*16);
                uint32_t vh4[4];
                LDSM_X4T(vh4[0], vh4[1], vh4[2], vh4[3], VHs + SW128(off));
                mma_f16(oc[np*2],   pH, &vh4[0]);
                mma_f16(oc[np*2+1], pH, &vh4[2]);
            }
        }
        __syncthreads();
    }

    // write context as single fp16 plane [B,S,D]
    const int bb = bh >> 4, hh = bh & 15;
#pragma unroll
    for (int n8 = 0; n8 < 8; n8++) {
        int dk = n8*8 + 2*tig;
        size_t e0 = ((size_t)bb*NS + r0)*ND + hh*64 + dk;
        *(uint32_t*)(ctx + e0*2) = f16x2_pack(oc[n8][0], oc[n8][1]);
        size_t e1 = ((size_t)bb*NS + r1)*ND + hh*64 + dk;
        *(uint32_t*)(ctx + e1*2) = f16x2_pack(oc[n8][2], oc[n8][3]);
    }

    // zero-fill masked upper region for this q-tile (streaming stores)
    if (write_attn && qb < (NS/128 - 1)) {
        int c0 = (qb + 1) * 128;
        int nv = (NS - c0) >> 2;
        for (int idx = tid; idx < 128*nv; idx += 256) {
            int r = idx / nv;
            int cc = (idx - r*nv) << 2;
            stg_cs_f4(attn + ((size_t)bh*NS + qb*128 + r)*NS + c0 + cc,
                      0.f, 0.f, 0.f, 0.f);
        }
    }
}

// ---------------------------------------------------------------------------
extern "C" void kernel_launch(void* const* d_in, const int* in_sizes, int n_in,
                              void* d_out, int out_size)
{
    (void)in_sizes; (void)n_in;
    const float* q  = (const float*)d_in[0];
    const float* k  = (const float*)d_in[1];
    const float* v  = (const float*)d_in[2];
    const float* wq = (const float*)d_in[4];
    const float* bq = (const float*)d_in[5];
    const float* wk = (const float*)d_in[6];
    const float* bk = (const float*)d_in[7];
    const float* wv = (const float*)d_in[8];
    const float* bv = (const float*)d_in[9];
    const float* wo = (const float*)d_in[10];
    const float* bo = (const float*)d_in[11];
    float* out = (float*)d_out;

    const long long OUT_ELEMS  = (long long)NM * ND;
    const long long ATTN_ELEMS = (long long)NBH * NS * NS;

    uint8_t *Qp, *KVp, *act, *w16, *ctx;
    float *Outd, *Ld;
    cudaGetSymbolAddress((void**)&Qp,  g_Qp);
    cudaGetSymbolAddress((void**)&KVp, g_KV);
    cudaGetSymbolAddress((void**)&act, g_act);
    cudaGetSymbolAddress((void**)&w16, g_w16);
    cudaGetSymbolAddress((void**)&ctx, g_ctx);
    cudaGetSymbolAddress((void**)&Outd, g_out);
    cudaGetSymbolAddress((void**)&Ld, g_l);

    float* outp  = out;
    float* attnp = nullptr;
    if ((long long)out_size >= OUT_ELEMS + ATTN_ELEMS) {
        attnp = out + OUT_ELEMS;
    } else if ((long long)out_size == ATTN_ELEMS) {
        attnp = out;
        outp  = Outd;
    }

    cudaFuncSetAttribute(gemm_qkv3, cudaFuncAttributeMaxDynamicSharedMemorySize, 65536);
    cudaFuncSetAttribute(gemm_out2, cudaFuncAttributeMaxDynamicSharedMemorySize, 65536);
    cudaFuncSetAttribute(attn_pass1, cudaFuncAttributeMaxDynamicSharedMemorySize, 49152);
    cudaFuncSetAttribute(attn_pass2, cudaFuncAttributeMaxDynamicSharedMemorySize, 49152);

    conv_acts<<<dim3(NM*ND/1024, 1, 3), 256>>>(q, k, v, act);
    conv_ws<<<dim3(ND*ND/1024, 1, 4), 256>>>(wq, wk, wv, wo, w16);

    dim3 ggrid(ND/128, NM/128, 3);
    gemm_qkv3<<<ggrid, 256, 65536>>>(act, w16, bq, bk, bv, Qp, KVp);

    dim3 agrid(NS/128, NBH);
    attn_pass1<<<agrid, 256, 49152>>>(Qp, KVp, Ld);
    attn_pass2<<<agrid, 256, 49152>>>(Qp, KVp, Ld, attnp, ctx, attnp ? 1 : 0);

    dim3 ogrid(ND/128, NM/128);
    gemm_out2<<<ogrid, 256, 65536>>>(ctx, w16, bo, outp);
}

// round 15
// speedup vs baseline: 1.0813x; 1.0813x over previous
#include <cuda_runtime.h>
#include <cstdint>

#define NB 4
#define NS 2048
#define ND 1024
#define NH 16
#define NDK 64
#define NBH (NB*NH)   /* 64 */
#define NM (NB*NS)    /* 8192 */

#define PLB ((size_t)NBH*NS*128)   /* bytes per 16-bit plane of one [BH,S,64] tensor */
#define ACTPB ((size_t)NM*ND*2)    /* bytes per fp16 activation plane [M,1024] */
#define WPB ((size_t)ND*ND*2)      /* bytes per fp16 weight plane */

#define LOG2E 1.4426950408889634f

// Scratch (allocation-free: __device__ globals)
__device__ __align__(128) uint8_t g_Qp[(size_t)NBH*NS*128];     // Q (fp16, *0.125*log2e)
__device__ __align__(128) uint8_t g_KV[2*(size_t)NBH*NS*128];   // K | V (fp16)
__device__ __align__(128) uint8_t g_act[3*ACTPB];               // q|k|v fp16
__device__ __align__(128) uint8_t g_w16[4*WPB];                 // wq|wk|wv|wo fp16
__device__ __align__(128) uint8_t g_ctx[ACTPB];                 // ctx fp16
__device__ float g_out[(size_t)NM*ND];

// ===========================================================================
// helpers
// ===========================================================================
__device__ __forceinline__ uint32_t smem_u32(const void* p) {
    uint32_t a;
    asm("{ .reg .u64 t; cvta.to.shared.u64 t, %1; cvt.u32.u64 %0, t; }"
        : "=r"(a) : "l"(p));
    return a;
}
__device__ __forceinline__ float ex2(float x) {
    float r;
    asm("ex2.approx.ftz.f32 %0, %1;" : "=f"(r) : "f"(x));
    return r;
}
#define LDSM_X4(r0, r1, r2, r3, addr) \
    asm volatile("ldmatrix.sync.aligned.m8n8.x4.shared.b16 {%0,%1,%2,%3}, [%4];" \
                 : "=r"(r0), "=r"(r1), "=r"(r2), "=r"(r3) : "r"(addr))
#define LDSM_X4T(r0, r1, r2, r3, addr) \
    asm volatile("ldmatrix.sync.aligned.m8n8.x4.trans.shared.b16 {%0,%1,%2,%3}, [%4];" \
                 : "=r"(r0), "=r"(r1), "=r"(r2), "=r"(r3) : "r"(addr))

__device__ __forceinline__ void mma_f16(float* d, const uint32_t* a, const uint32_t* b) {
    asm volatile("mma.sync.aligned.m16n8k16.row.col.f32.f16.f16.f32 "
                 "{%0,%1,%2,%3}, {%4,%5,%6,%7}, {%8,%9}, {%0,%1,%2,%3};"
                 : "+f"(d[0]), "+f"(d[1]), "+f"(d[2]), "+f"(d[3])
                 : "r"(a[0]), "r"(a[1]), "r"(a[2]), "r"(a[3]),
                   "r"(b[0]), "r"(b[1]));
}

__device__ __forceinline__ uint32_t f16x2_pack(float x0, float x1) {
    uint32_t r;
    asm("cvt.rn.f16x2.f32 %0, %1, %2;" : "=r"(r) : "f"(x1), "f"(x0));
    return r;
}
#define SW128(off) ((off) ^ (((off) >> 3) & 0x70))

__device__ __forceinline__ void cp16(uint32_t dst, const uint8_t* src) {
    asm volatile("{ .reg .u64 gp; cvta.to.global.u64 gp, %1; "
                 "cp.async.cg.shared.global [%0], [gp], 16; }"
                 :: "r"(dst), "l"(src));
}
#define CP_COMMIT() asm volatile("cp.async.commit_group;" ::: "memory")
#define CP_WAIT1()  asm volatile("cp.async.wait_group 1;" ::: "memory")
#define CP_WAIT0()  asm volatile("cp.async.wait_group 0;" ::: "memory")

__device__ __forceinline__ void stg_cs_f2(float* p, float x, float y) {
    asm volatile("st.global.cs.v2.f32 [%0], {%1,%2};"
                 :: "l"(p), "f"(x), "f"(y) : "memory");
}
__device__ __forceinline__ void stg_cs_f4(float* p, float x, float y, float z, float w) {
    asm volatile("st.global.cs.v4.f32 [%0], {%1,%2,%3,%4};"
                 :: "l"(p), "f"(x), "f"(y), "f"(z), "f"(w) : "memory");
}

// ===========================================================================
// Conversion pre-passes (single fp16 plane each)
// ===========================================================================
__global__ __launch_bounds__(256)
void conv_acts(const float* __restrict__ q, const float* __restrict__ k,
               const float* __restrict__ v, uint8_t* __restrict__ act)
{
    const int z = blockIdx.z;
    const float* src = (z == 0) ? q : (z == 1) ? k : v;
    size_t idx = (size_t)blockIdx.x * 256 + threadIdx.x;
    float4 x = ((const float4*)src)[idx];
    uint32_t a = f16x2_pack(x.x, x.y);
    uint32_t b = f16x2_pack(x.z, x.w);
    ((uint2*)act)[(size_t)z * (ACTPB / 8) + idx] = make_uint2(a, b);
}

__global__ __launch_bounds__(256)
void conv_ws(const float* __restrict__ wq, const float* __restrict__ wk,
             const float* __restrict__ wv, const float* __restrict__ wo,
             uint8_t* __restrict__ w16)
{
    const int z = blockIdx.z;
    const float* src = (z == 0) ? wq : (z == 1) ? wk : (z == 2) ? wv : wo;
    size_t idx = (size_t)blockIdx.x * 256 + threadIdx.x;
    float4 x = ((const float4*)src)[idx];
    uint32_t a = f16x2_pack(x.x, x.y);
    uint32_t b = f16x2_pack(x.z, x.w);
    ((uint2*)w16)[(size_t)z * (WPB / 8) + idx] = make_uint2(a, b);
}

// ===========================================================================
// fp16 GEMM (R12 body): BM=64, BN=128, BK=64, 16 chunks, 2-stage cp.async.
// 256 threads (8 warps 2m x 4n), warp tile 32x32.
// Stage: A(8K) B(16K) = 24KB; x2 = 48KB dynamic smem.
// ===========================================================================
#define G2_STG 24576u

template<int MODE>
__device__ __forceinline__
void gemm2_body(const uint8_t* __restrict__ Ah, const uint8_t* __restrict__ Wh,
                const float* __restrict__ bias, void* __restrict__ Cout,
                float scale, uint32_t sb)
{
    const int tid  = threadIdx.x;
    const int wid  = tid >> 5, lane = tid & 31;
    const int m0 = blockIdx.y << 6;
    const int n0 = blockIdx.x << 7;
    const int mwOff = (wid & 1) * 32;
    const int nwOff = (wid >> 1) * 32;

    const int lrow = tid >> 3;
    const int lchk = tid & 7;

    {
        const uint32_t st = sb;
#pragma unroll
        for (int rr = 0; rr < 2; rr++) {
            int row = rr*32 + lrow;
            uint32_t off = (uint32_t)(row*128 + lchk*16);
            cp16(st + SW128(off), Ah + (size_t)(m0 + row)*2048 + lchk*16);
        }
#pragma unroll
        for (int rr = 0; rr < 4; rr++) {
            int row = rr*32 + lrow;
            uint32_t off = (uint32_t)(row*128 + lchk*16);
            cp16(st + 8192 + SW128(off), Wh + (size_t)(n0 + row)*2048 + lchk*16);
        }
    }
    CP_COMMIT();

    float d[2][4][4];
#pragma unroll
    for (int mt = 0; mt < 2; mt++)
#pragma unroll
        for (int nt = 0; nt < 4; nt++)
#pragma unroll
            for (int e = 0; e < 4; e++) d[mt][nt][e] = 0.f;

    for (int ch = 0; ch < 16; ch++) {
        if (ch + 1 < 16) {
            const uint32_t st = sb + (uint32_t)((ch+1) & 1) * G2_STG;
            const int k0b = (ch + 1) * 128;
#pragma unroll
            for (int rr = 0; rr < 2; rr++) {
                int row = rr*32 + lrow;
                uint32_t off = (uint32_t)(row*128 + lchk*16);
                cp16(st + SW128(off), Ah + (size_t)(m0 + row)*2048 + k0b + lchk*16);
            }
#pragma unroll
            for (int rr = 0; rr < 4; rr++) {
                int row = rr*32 + lrow;
                uint32_t off = (uint32_t)(row*128 + lchk*16);
                cp16(st + 8192 + SW128(off),
                     Wh + (size_t)(n0 + row)*2048 + k0b + lchk*16);
            }
        }
        CP_COMMIT();
        CP_WAIT1();
        __syncthreads();

        const uint32_t cur = sb + (uint32_t)(ch & 1) * G2_STG;
#pragma unroll
        for (int ks = 0; ks < 4; ks++) {
            uint32_t aHi[2][4], bHi[2][4];
#pragma unroll
            for (int mt = 0; mt < 2; mt++) {
                uint32_t off = (uint32_t)((mwOff + mt*16 + (lane & 15))*128
                                          + ks*32 + (lane >> 4)*16);
                LDSM_X4(aHi[mt][0], aHi[mt][1], aHi[mt][2], aHi[mt][3],
                        cur + SW128(off));
            }
#pragma unroll
            for (int nt2 = 0; nt2 < 2; nt2++) {
                uint32_t off = (uint32_t)((nwOff + nt2*16 + (lane>>4)*8 + (lane&7))*128
                                          + ks*32 + ((lane>>3)&1)*16);
                LDSM_X4(bHi[nt2][0], bHi[nt2][1], bHi[nt2][2], bHi[nt2][3],
                        cur + 8192 + SW128(off));
            }
#pragma unroll
            for (int mt = 0; mt < 2; mt++) {
#pragma unroll
                for (int nt = 0; nt < 4; nt++) {
                    mma_f16(d[mt][nt], aHi[mt], &bHi[nt >> 1][(nt & 1) * 2]);
                }
            }
        }
        __syncthreads();
    }

    const int g = lane >> 2, tig = lane & 3;
#pragma unroll
    for (int mt = 0; mt < 2; mt++) {
#pragma unroll
        for (int nt = 0; nt < 4; nt++) {
            int col = n0 + nwOff + nt*8 + 2*tig;
            float2 bb = *(const float2*)&bias[col];
#pragma unroll
            for (int half = 0; half < 2; half++) {
                int row = m0 + mwOff + mt*16 + g + half*8;
                float ox = (d[mt][nt][half*2+0] + bb.x) * scale;
                float oy = (d[mt][nt][half*2+1] + bb.y) * scale;
                if (MODE == 0) {
                    *(float2*)((float*)Cout + (size_t)row * ND + col) = make_float2(ox, oy);
                } else {
                    int bb2 = row >> 11;
                    int ss  = row & (NS - 1);
                    int hh  = col >> 6;
                    int dd  = col & (NDK - 1);
                    size_t boff = ((size_t)(bb2*NH + hh)*NS + ss)*128 + dd*2;
                    *(uint32_t*)((uint8_t*)Cout + boff) = f16x2_pack(ox, oy);
                }
            }
        }
    }
}

__global__ __launch_bounds__(256)
void gemm_qkv3(const uint8_t* __restrict__ act, const uint8_t* __restrict__ w16,
               const float* __restrict__ bq, const float* __restrict__ bk,
               const float* __restrict__ bv,
               uint8_t* __restrict__ Qp, uint8_t* __restrict__ KVp)
{
    extern __shared__ uint8_t smraw[];
    const uint32_t sb = smem_u32(smraw);
    const int z = blockIdx.z;
    const uint8_t* Ah = act + (size_t)z * ACTPB;
    const uint8_t* Wh = w16 + (size_t)z * WPB;
    const float* bias = (z == 0) ? bq : (z == 1) ? bk : bv;
    uint8_t* out = (z == 0) ? Qp : (z == 1) ? KVp : (KVp + PLB);
    float scale = (z == 0) ? (0.125f * LOG2E) : 1.0f;
    gemm2_body<1>(Ah, Wh, bias, out, scale, sb);
}

__global__ __launch_bounds__(256)
void gemm_out2(const uint8_t* __restrict__ ctx, const uint8_t* __restrict__ w16,
               const float* __restrict__ bias, float* __restrict__ C)
{
    extern __shared__ uint8_t smraw[];
    const uint32_t sb = smem_u32(smraw);
    gemm2_body<0>(ctx, w16 + 3*WPB, bias, C, 1.0f, sb);
}

// ===========================================================================
// FUSED attention: sweep 1 computes l = sum 2^s in registers (K-only,
// 128-wide tiles); sweep 2 recomputes S, writes attn (streaming), O += P@V.
// Cross-CTA overlap hides sweep-1 compute under sweep-2's store roofline.
// dyn smem: Q(16K) + 2 stages x 16K = 48KB (stages reused across sweeps).
// ===========================================================================
__global__ __launch_bounds__(256)
void attn_fused(const uint8_t* __restrict__ Qp, const uint8_t* __restrict__ KV,
                float* __restrict__ attn, uint8_t* __restrict__ ctx,
                int write_attn)
{
    extern __shared__ uint8_t smraw[];
    const uint32_t sb = smem_u32(smraw);
    const uint32_t QH = sb;
    const uint32_t ST = sb + 16384;

    const int qb = gridDim.x - 1 - blockIdx.x;
    const int bh = blockIdx.y;
    const int tid = threadIdx.x, w = tid >> 5, lane = tid & 31;
    const int g = lane >> 2, tig = lane & 3;

    const uint8_t* Qg = Qp + (size_t)bh*NS*128 + (size_t)qb*128*128;
    const uint8_t* Kg = KV + (size_t)bh*NS*128;   // plane 0 = K, plane 1 = V

    // Q tile (persistent for both sweeps)
#pragma unroll
    for (int rr = 0; rr < 4; rr++) {
        int idx = rr*256 + tid;
        int row = idx >> 3, chk = idx & 7;
        uint32_t off = (uint32_t)(row*128 + chk*16);
        cp16(QH + SW128(off), Qg + off);
    }
    CP_COMMIT();
    // sweep-1 prologue: K tile 0 (128 rows)
#pragma unroll
    for (int rr = 0; rr < 4; rr++) {
        int idx = rr*256 + tid;
        int row = idx >> 3, chk = idx & 7;
        uint32_t off = (uint32_t)(row*128 + chk*16);
        cp16(ST + SW128(off), Kg + off);
    }
    CP_COMMIT();
    CP_WAIT1();
    __syncthreads();

    uint32_t aQh[4][4];
#pragma unroll
    for (int ks = 0; ks < 4; ks++) {
        uint32_t off = (uint32_t)((w*16 + (lane & 15))*128 + ks*32 + (lane>>4)*16);
        LDSM_X4(aQh[ks][0], aQh[ks][1], aQh[ks][2], aQh[ks][3], QH + SW128(off));
    }

    const int r0 = qb*128 + w*16 + g, r1 = r0 + 8;

    // ---------------- sweep 1: l over 128-wide K tiles ----------------
    const int nt1 = qb + 1;
    float l0 = 0.f, l1 = 0.f;

    for (int kt = 0; kt < nt1; kt++) {
        if (kt + 1 < nt1) {
            uint32_t st = ST + ((kt+1)&1)*16384;
#pragma unroll
            for (int rr = 0; rr < 4; rr++) {
                int idx = rr*256 + tid;
                int row = idx >> 3, chk = idx & 7;
                uint32_t off = (uint32_t)(row*128 + chk*16);
                cp16(st + SW128(off), Kg + (size_t)((kt+1)*128+row)*128 + chk*16);
            }
        }
        CP_COMMIT();
        CP_WAIT1();
        __syncthreads();

        const uint32_t KHs = ST + (kt&1)*16384;
#pragma unroll
        for (int half = 0; half < 2; half++) {
            float c[8][4];
#pragma unroll
            for (int n8 = 0; n8 < 8; n8++)
#pragma unroll
                for (int e = 0; e < 4; e++) c[n8][e] = 0.f;

#pragma unroll
            for (int ks = 0; ks < 4; ks++) {
#pragma unroll
                for (int np = 0; np < 4; np++) {
                    uint32_t off = (uint32_t)((half*64 + np*16 + (lane>>4)*8 + (lane&7))*128
                                              + ks*32 + ((lane>>3)&1)*16);
                    uint32_t bh4[4];
                    LDSM_X4(bh4[0], bh4[1], bh4[2], bh4[3], KHs + SW128(off));
                    mma_f16(c[np*2],   aQh[ks], &bh4[0]);
                    mma_f16(c[np*2+1], aQh[ks], &bh4[2]);
                }
            }

            if (kt == nt1 - 1) {
#pragma unroll
                for (int n8 = 0; n8 < 8; n8++) {
                    int col = kt*128 + half*64 + n8*8 + 2*tig;
                    if (col   > r0) c[n8][0] = -1e30f;
                    if (col+1 > r0) c[n8][1] = -1e30f;
                    if (col   > r1) c[n8][2] = -1e30f;
                    if (col+1 > r1) c[n8][3] = -1e30f;
                }
            }

#pragma unroll
            for (int n8 = 0; n8 < 8; n8++) {
                l0 += ex2(c[n8][0]) + ex2(c[n8][1]);
                l1 += ex2(c[n8][2]) + ex2(c[n8][3]);
            }
        }
        __syncthreads();
    }

    l0 += __shfl_xor_sync(0xffffffffu, l0, 1);
    l0 += __shfl_xor_sync(0xffffffffu, l0, 2);
    l1 += __shfl_xor_sync(0xffffffffu, l1, 1);
    l1 += __shfl_xor_sync(0xffffffffu, l1, 2);
    const float il0 = 1.0f / l0;
    const float il1 = 1.0f / l1;

    // ---------------- sweep 2: attn store + P@V over 64-row KV tiles ----
    CP_WAIT0();
    __syncthreads();

    // sweep-2 prologue: KV tile 0 (K 8K | V 8K)
#pragma unroll
    for (int rr = 0; rr < 4; rr++) {
        int idx = rr*256 + tid;
        int pl = idx >> 9, wi = idx & 511;
        int row = wi >> 3, chk = wi & 7;
        uint32_t off = (uint32_t)(row*128 + chk*16);
        cp16(ST + pl*8192 + SW128(off), Kg + (size_t)pl*PLB + off);
    }
    CP_COMMIT();

    const int nt2 = 2*qb + 2;
    float oc[8][4];
#pragma unroll
    for (int n8 = 0; n8 < 8; n8++)
#pragma unroll
        for (int e = 0; e < 4; e++) oc[n8][e] = 0.f;

    for (int kt = 0; kt < nt2; kt++) {
        if (kt + 1 < nt2) {
            uint32_t st = ST + ((kt+1)&1)*16384;
#pragma unroll
            for (int rr = 0; rr < 4; rr++) {
                int idx = rr*256 + tid;
                int pl = idx >> 9, wi = idx & 511;
                int row = wi >> 3, chk = wi & 7;
                uint32_t off = (uint32_t)(row*128 + chk*16);
                cp16(st + pl*8192 + SW128(off),
                     Kg + (size_t)pl*PLB + (size_t)((kt+1)*64+row)*128 + chk*16);
            }
        }
        CP_COMMIT();
        CP_WAIT1();
        __syncthreads();

        const uint32_t B0 = ST + (kt&1)*16384;
        const uint32_t KHs = B0, VHs = B0 + 8192;

        float c[8][4];
#pragma unroll
        for (int n8 = 0; n8 < 8; n8++)
#pragma unroll
            for (int e = 0; e < 4; e++) c[n8][e] = 0.f;

#pragma unroll
        for (int ks = 0; ks < 4; ks++) {
#pragma unroll
            for (int np = 0; np < 4; np++) {
                uint32_t off = (uint32_t)((np*16 + (lane>>4)*8 + (lane&7))*128
                                          + ks*32 + ((lane>>3)&1)*16);
                uint32_t bh4[4];
                LDSM_X4(bh4[0], bh4[1], bh4[2], bh4[3], KHs + SW128(off));
                mma_f16(c[np*2],   aQh[ks], &bh4[0]);
                mma_f16(c[np*2+1], aQh[ks], &bh4[2]);
            }
        }

        if (kt >= 2*qb) {
#pragma unroll
            for (int n8 = 0; n8 < 8; n8++) {
                int col = kt*64 + n8*8 + 2*tig;
                if (col   > r0) c[n8][0] = -1e30f;
                if (col+1 > r0) c[n8][1] = -1e30f;
                if (col   > r1) c[n8][2] = -1e30f;
                if (col+1 > r1) c[n8][3] = -1e30f;
            }
        }

#pragma unroll
        for (int n8 = 0; n8 < 8; n8++) {
            c[n8][0] = ex2(c[n8][0])*il0;
            c[n8][1] = ex2(c[n8][1])*il0;
            c[n8][2] = ex2(c[n8][2])*il1;
            c[n8][3] = ex2(c[n8][3])*il1;
        }

        if (write_attn) {
            size_t ro0 = ((size_t)bh*NS + r0)*NS + (size_t)kt*64;
            size_t ro1 = ((size_t)bh*NS + r1)*NS + (size_t)kt*64;
#pragma unroll
            for (int n8 = 0; n8 < 8; n8++) {
                int col = n8*8 + 2*tig;
                stg_cs_f2(attn + ro0 + col, c[n8][0], c[n8][1]);
                stg_cs_f2(attn + ro1 + col, c[n8][2], c[n8][3]);
            }
        }

        // P @ V
#pragma unroll
        for (int ks = 0; ks < 4; ks++) {
            uint32_t pH[4];
            pH[0] = f16x2_pack(c[2*ks][0],   c[2*ks][1]);
            pH[1] = f16x2_pack(c[2*ks][2],   c[2*ks][3]);
            pH[2] = f16x2_pack(c[2*ks+1][0], c[2*ks+1][1]);
            pH[3] = f16x2_pack(c[2*ks+1][2], c[2*ks+1][3]);
#pragma unroll
            for (int np = 0; np < 4; np++) {
                uint32_t off = (uint32_t)((ks*16 + ((lane>>3)&1)*8 + (lane&7))*128
                                          + np*32 + (lane>>4)*16);
                uint32_t vh4[4];
                LDSM_X4T(vh4[0], vh4[1], vh4[2], vh4[3], VHs + SW128(off));
                mma_f16(oc[np*2],   pH, &vh4[0]);
                mma_f16(oc[np*2+1], pH, &vh4[2]);
            }
        }
        __syncthreads();
    }

    // write context as single fp16 plane [B,S,D]
    const int bb = bh >> 4, hh = bh & 15;
#pragma unroll
    for (int n8 = 0; n8 < 8; n8++) {
        int dk = n8*8 + 2*tig;
        size_t e0 = ((size_t)bb*NS + r0)*ND + hh*64 + dk;
        *(uint32_t*)(ctx + e0*2) = f16x2_pack(oc[n8][0], oc[n8][1]);
        size_t e1 = ((size_t)bb*NS + r1)*ND + hh*64 + dk;
        *(uint32_t*)(ctx + e1*2) = f16x2_pack(oc[n8][2], oc[n8][3]);
    }

    // zero-fill masked upper region for this q-tile (streaming stores)
    if (write_attn && qb < (NS/128 - 1)) {
        int c0 = (qb + 1) * 128;
        int nv = (NS - c0) >> 2;
        for (int idx = tid; idx < 128*nv; idx += 256) {
            int r = idx / nv;
            int cc = (idx - r*nv) << 2;
            stg_cs_f4(attn + ((size_t)bh*NS + qb*128 + r)*NS + c0 + cc,
                      0.f, 0.f, 0.f, 0.f);
        }
    }
}

// ---------------------------------------------------------------------------
extern "C" void kernel_launch(void* const* d_in, const int* in_sizes, int n_in,
                              void* d_out, int out_size)
{
    (void)in_sizes; (void)n_in;
    const float* q  = (const float*)d_in[0];
    const float* k  = (const float*)d_in[1];
    const float* v  = (const float*)d_in[2];
    const float* wq = (const float*)d_in[4];
    const float* bq = (const float*)d_in[5];
    const float* wk = (const float*)d_in[6];
    const float* bk = (const float*)d_in[7];
    const float* wv = (const float*)d_in[8];
    const float* bv = (const float*)d_in[9];
    const float* wo = (const float*)d_in[10];
    const float* bo = (const float*)d_in[11];
    float* out = (float*)d_out;

    const long long OUT_ELEMS  = (long long)NM * ND;
    const long long ATTN_ELEMS = (long long)NBH * NS * NS;

    uint8_t *Qp, *KVp, *act, *w16, *ctx;
    float *Outd;
    cudaGetSymbolAddress((void**)&Qp,  g_Qp);
    cudaGetSymbolAddress((void**)&KVp, g_KV);
    cudaGetSymbolAddress((void**)&act, g_act);
    cudaGetSymbolAddress((void**)&w16, g_w16);
    cudaGetSymbolAddress((void**)&ctx, g_ctx);
    cudaGetSymbolAddress((void**)&Outd, g_out);

    float* outp  = out;
    float* attnp = nullptr;
    if ((long long)out_size >= OUT_ELEMS + ATTN_ELEMS) {
        attnp = out + OUT_ELEMS;
    } else if ((long long)out_size == ATTN_ELEMS) {
        attnp = out;
        outp  = Outd;
    }

    cudaFuncSetAttribute(gemm_qkv3, cudaFuncAttributeMaxDynamicSharedMemorySize, 49152);
    cudaFuncSetAttribute(gemm_out2, cudaFuncAttributeMaxDynamicSharedMemorySize, 49152);
    cudaFuncSetAttribute(attn_fused, cudaFuncAttributeMaxDynamicSharedMemorySize, 49152);

    conv_acts<<<dim3(NM*ND/1024, 1, 3), 256>>>(q, k, v, act);
    conv_ws<<<dim3(ND*ND/1024, 1, 4), 256>>>(wq, wk, wv, wo, w16);

    dim3 ggrid(ND/128, NM/64, 3);
    gemm_qkv3<<<ggrid, 256, 49152>>>(act, w16, bq, bk, bv, Qp, KVp);

    dim3 agrid(NS/128, NBH);
    attn_fused<<<agrid, 256, 49152>>>(Qp, KVp, attnp, ctx, attnp ? 1 : 0);

    dim3 ogrid(ND/128, NM/64);
    gemm_out2<<<ogrid, 256, 49152>>>(ctx, w16, bo, outp);
}